// round 16
// baseline (speedup 1.0000x reference)
#include <cuda_runtime.h>

#define RES   320
#define NB    32
#define NPIX  (RES*RES)        // 102400
#define NSKIP 21769.0f         // count of trajectory points zeroed by the skip mask

typedef unsigned long long u64;

// 26.2 MB scratch: row-FFT output, complex packed (re,im) u64, [b][iy][kx natural]
__device__ __align__(16) u64 g_grid[NB * NPIX];
// work-queue state (reset each launch by k_reset)
__device__ unsigned g_ticket;
__device__ unsigned g_done[NB];

// ---------------- packed f32x2 helpers (sm_103a) ----------------
__device__ __forceinline__ u64 pk2(float x, float y){
    u64 r; asm("mov.b64 %0, {%1, %2};" : "=l"(r) : "r"(__float_as_uint(x)), "r"(__float_as_uint(y))); return r;
}
__device__ __forceinline__ void unpk2(u64 a, float &x, float &y){
    unsigned lo, hi;
    asm("mov.b64 {%0, %1}, %2;" : "=r"(lo), "=r"(hi) : "l"(a));
    x = __uint_as_float(lo); y = __uint_as_float(hi);
}
__device__ __forceinline__ u64 padd(u64 a, u64 b){ u64 r; asm("add.rn.f32x2 %0, %1, %2;" : "=l"(r) : "l"(a), "l"(b)); return r; }
__device__ __forceinline__ u64 pmul(u64 a, u64 b){ u64 r; asm("mul.rn.f32x2 %0, %1, %2;" : "=l"(r) : "l"(a), "l"(b)); return r; }
__device__ __forceinline__ u64 pfma(u64 a, u64 b, u64 c){ u64 r; asm("fma.rn.f32x2 %0, %1, %2, %3;" : "=l"(r) : "l"(a), "l"(b), "l"(c)); return r; }

// ---------------- SoA packed 5-point inverse DFT (exponent +i) --------------
__device__ __forceinline__ void dft5_soa(const u64* xr, const u64* xi, u64* Xr, u64* Xi){
    const u64 NEG1 = pk2(-1.f, -1.f);
    const u64 C1 = pk2( 0.30901699437494742f,  0.30901699437494742f);
    const u64 C2 = pk2(-0.80901699437494745f, -0.80901699437494745f);
    const u64 S1 = pk2( 0.95105651629515357f,  0.95105651629515357f);
    const u64 S2 = pk2( 0.58778525229247314f,  0.58778525229247314f);
    const u64 NS1= pk2(-0.95105651629515357f, -0.95105651629515357f);
    u64 t1r = padd(xr[1], xr[4]), t1i = padd(xi[1], xi[4]);
    u64 t2r = padd(xr[2], xr[3]), t2i = padd(xi[2], xi[3]);
    u64 t3r = pfma(xr[4], NEG1, xr[1]), t3i = pfma(xi[4], NEG1, xi[1]);
    u64 t4r = pfma(xr[3], NEG1, xr[2]), t4i = pfma(xi[3], NEG1, xi[2]);
    Xr[0] = padd(xr[0], padd(t1r, t2r));
    Xi[0] = padd(xi[0], padd(t1i, t2i));
    u64 a1r = pfma(t1r, C1, pfma(t2r, C2, xr[0])), a1i = pfma(t1i, C1, pfma(t2i, C2, xi[0]));
    u64 b1r = pfma(t4r, S2, pmul(t3r, S1)),        b1i = pfma(t4i, S2, pmul(t3i, S1));
    u64 a2r = pfma(t1r, C2, pfma(t2r, C1, xr[0])), a2i = pfma(t1i, C2, pfma(t2i, C1, xi[0]));
    u64 b2r = pfma(t4r, NS1, pmul(t3r, S2)),       b2i = pfma(t4i, NS1, pmul(t3i, S2));
    Xr[1] = pfma(b1i, NEG1, a1r);  Xi[1] = padd(a1i, b1r);
    Xr[4] = padd(a1r, b1i);        Xi[4] = pfma(b1r, NEG1, a1i);
    Xr[2] = pfma(b2i, NEG1, a2r);  Xi[2] = padd(a2i, b2r);
    Xr[3] = padd(a2r, b2i);        Xi[3] = pfma(b2r, NEG1, a2i);
}

// ---------------------------------------------------------------------------
// Dual 320-point inverse DFT (unnormalized, exponent +i), SoA across the two
// f32x2 halves. Exit: element X[32*k1 + k2] in re[k1]/im[k1], k2 = brev5(lane).
// ---------------------------------------------------------------------------
__device__ __forceinline__ void warp_fft320_soa(u64* re, u64* im, int lane, int k2){
    const float TWO_PI = 6.2831853071795865f;
    const u64 POS1 = pk2(1.f, 1.f);
    const u64 NEG1 = pk2(-1.f, -1.f);
    float twc[4], twn[4];
    #pragma unroll
    for (int s = 0; s < 4; s++){
        int half = 16 >> s;
        float ang = TWO_PI * (float)(lane & (half-1)) / (float)(2*half);
        __sincosf(ang, &twn[s], &twc[s]);
    }
    #pragma unroll
    for (int s = 0; s < 5; s++){
        int half = 16 >> s;
        bool up = (lane & half) != 0;
        u64 Spm = up ? NEG1 : POS1;
        u64 C = POS1, S = 0ull, NS = 0ull;
        if (s < 4 && up){ C = pk2(twc[s], twc[s]); S = pk2(twn[s], twn[s]); NS = pk2(-twn[s], -twn[s]); }
        #pragma unroll
        for (int j = 0; j < 10; j++){
            float ax, ay;
            unpk2(re[j], ax, ay);
            float bx = __shfl_xor_sync(0xffffffffu, ax, half);
            float by = __shfl_xor_sync(0xffffffffu, ay, half);
            u64 rr = pfma(re[j], Spm, pk2(bx, by));
            unpk2(im[j], ax, ay);
            bx = __shfl_xor_sync(0xffffffffu, ax, half);
            by = __shfl_xor_sync(0xffffffffu, ay, half);
            u64 ri = pfma(im[j], Spm, pk2(bx, by));
            if (s < 4){
                re[j] = pfma(ri, NS, pmul(rr, C));
                im[j] = pfma(ri, C,  pmul(rr, S));
            } else { re[j] = rr; im[j] = ri; }
        }
    }
    {
        float s1, c1;
        __sincosf(TWO_PI * (float)k2 * (1.0f/320.0f), &s1, &c1);
        float cj = c1, sj = s1;
        #pragma unroll
        for (int j = 1; j < 10; j++){
            u64 C = pk2(cj, cj), S = pk2(sj, sj), NS = pk2(-sj, -sj);
            u64 t   = pmul(re[j], C);
            u64 nim = pfma(im[j], C, pmul(re[j], S));
            re[j] = pfma(im[j], NS, t);
            im[j] = nim;
            if (j < 9){
                float cn = cj*c1 - sj*s1;
                float sn = cj*s1 + sj*c1;
                cj = cn; sj = sn;
            }
        }
    }
    {
        u64 Er[5], Ei[5], Or[5], Oi[5];
        {
            u64 xr[5] = { re[0], re[2], re[4], re[6], re[8] };
            u64 xi[5] = { im[0], im[2], im[4], im[6], im[8] };
            dft5_soa(xr, xi, Er, Ei);
        }
        {
            u64 xr[5] = { re[1], re[3], re[5], re[7], re[9] };
            u64 xi[5] = { im[1], im[3], im[5], im[7], im[9] };
            dft5_soa(xr, xi, Or, Oi);
        }
        const float wc[5] = {1.f, 0.80901699437494745f, 0.30901699437494742f, -0.30901699437494742f, -0.80901699437494745f};
        const float ws[5] = {0.f, 0.58778525229247314f, 0.95105651629515357f,  0.95105651629515357f,  0.58778525229247314f};
        #pragma unroll
        for (int k = 0; k < 5; k++){
            u64 wor, woi;
            if (k == 0){ wor = Or[0]; woi = Oi[0]; }
            else {
                u64 C = pk2(wc[k], wc[k]), S = pk2(ws[k], ws[k]), NS = pk2(-ws[k], -ws[k]);
                wor = pfma(Oi[k], NS, pmul(Or[k], C));
                woi = pfma(Oi[k], C,  pmul(Or[k], S));
            }
            re[k]   = padd(Er[k], wor);
            im[k]   = padd(Ei[k], woi);
            re[k+5] = pfma(wor, NEG1, Er[k]);
            im[k+5] = pfma(woi, NEG1, Ei[k]);
        }
    }
}

// fractional coordinate, replicating the reference's fp32 op sequence exactly
__device__ __forceinline__ float frac_of(int idx){
    float t = (float)(idx - 160);
    float g = t * 0.00625f;
    float x = ((g + 1.0f)*320.0f - 1.0f)*0.5f;
    return x - floorf(x);
}

// gridding stencil for one output row qy (col x at slot x+1 in row pointers)
__device__ __forceinline__ void stencil_row(const u64* rowU, const u64* rowV, const u64* rowW,
                                            int qy, int lane, u64* v){
    float fy0 = frac_of(qy);
    float fy1 = frac_of(qy + 1);
    float mj0 = (!(qy >= 120 && qy <= 160)) ? 1.f : 0.f;
    float mj1 = (qy + 1 < 320 && !(qy + 1 >= 120 && qy + 1 <= 160)) ? 1.f : 0.f;
    u64 K0p = pk2(mj0 * fy0,          mj0 * fy0);
    u64 K1p = pk2(mj1 * (1.0f - fy1), mj1 * (1.0f - fy1));
    u64 AY0 = pk2(1.0f - fy0, 1.0f - fy0);
    u64 BY0 = pk2(fy0, fy0);
    u64 AY1 = pk2(1.0f - fy1, 1.0f - fy1);
    u64 BY1 = pk2(fy1, fy1);

    int qx0 = 10*lane;
    u64 TLp0 = 0ull, TLp1 = 0ull;
    u64 cu0 = rowU[qx0], cv0 = rowV[qx0], cw0 = rowW[qx0];

    #pragma unroll
    for (int s = 0; s <= 10; s++){
        int I = qx0 + s;
        u64 cu1 = rowU[I+1];
        u64 cv1 = rowV[I+1];
        u64 cw1 = rowW[I+1];
        float fx = frac_of(I);
        float a = 1.0f - fx;
        float mi = (I < 320 && !(I >= 140 && I <= 170)) ? 1.f : 0.f;
        u64 Ap = pk2(a, a), Bp = pk2(fx, fx);
        u64 cxu = pfma(cu1, Bp, pmul(cu0, Ap));
        u64 cxv = pfma(cv1, Bp, pmul(cv0, Ap));
        u64 cxw = pfma(cw1, Bp, pmul(cw0, Ap));
        u64 sub0 = pfma(cxv, BY0, pmul(cxu, AY0));
        u64 sub1 = pfma(cxw, BY1, pmul(cxv, AY1));
        u64 WL = pk2(mi*fx, mi*fx), WR = pk2(mi*a, mi*a);
        u64 TL0 = pmul(sub0, WL), TR0 = pmul(sub0, WR);
        u64 TL1 = pmul(sub1, WL), TR1 = pmul(sub1, WR);
        if (s > 0){
            v[s-1] = pfma(padd(TLp1, TR1), K1p, pmul(padd(TLp0, TR0), K0p));
        }
        TLp0 = TL0; TLp1 = TL1;
        cu0 = cu1; cv0 = cv1; cw0 = cw1;
    }
}

#define PADIX(i) ((i) + ((i)>>3))
#define SH_U64   5796                  // union: rows 18*322=5796, cols 2*8*361=5776

// ---------------- reset kernel (graph-replay determinism) ----------------
__global__ void k_reset(){
    if (threadIdx.x == 0) g_ticket = 0u;
    if (threadIdx.x < NB) g_done[threadIdx.x] = 0u;
}

// ---------------------------------------------------------------------------
// Fused persistent kernel: ticket queue over 1280 units.
// t in [0,640): row-unit   b = t/20, base = (t%20)*16  (16 rows, 8 warps x dual)
// t in [640,1280): col-unit b = u/20, v0 = (u%20)*16   (16 cols, 8 warps x dual)
// Col-units spin until g_done[b] == 20.
// ---------------------------------------------------------------------------
__global__ __launch_bounds__(256) void k_fused(const float* __restrict__ ksp,
                                               float* __restrict__ out){
    __shared__ u64 buf[SH_U64];
    __shared__ unsigned sh_t;
    int tid  = threadIdx.x;
    int warp = tid >> 5;
    int lane = tid & 31;
    int k2 = __brev((unsigned)lane) >> 27;

    for (;;){
        if (tid == 0) sh_t = atomicAdd(&g_ticket, 1u);
        __syncthreads();
        unsigned t = sh_t;
        if (t >= 1280u) return;

        if (t < 640u){
            // ---------------- row-unit: stencil + dual row FFTs ----------------
            int b    = t / 20;
            int base = (t % 20) * 16;
            u64 (*shc)[322] = (u64(*)[322])buf;   // [18][322]
            const u64* cb = (const u64*)(ksp + (size_t)b * (2*NPIX));

            for (int idx = tid; idx < 18*320; idx += 256){
                int s = idx / 320, x = idx - 320*s;
                int r = base - 1 + s;
                shc[s][1 + x] = (r >= 0 && r < RES) ? cb[r*RES + x] : 0ull;
            }
            if (tid < 36){
                int s = tid >> 1;
                shc[s][(tid & 1) ? 321 : 0] = 0ull;
            }
            __syncthreads();

            int qyA = base + 2*warp;
            u64 vA[10], vB[10];
            stencil_row(shc[2*warp],   shc[2*warp+1], shc[2*warp+2], qyA,     lane, vA);
            stencil_row(shc[2*warp+1], shc[2*warp+2], shc[2*warp+3], qyA + 1, lane, vB);
            if (qyA == 0 && lane == 0){
                vA[0] = pfma(shc[1][1], pk2(NSKIP*0.0625f, NSKIP*0.0625f), vA[0]);
            }

            u64 re[10], im[10];
            #pragma unroll
            for (int j = 0; j < 10; j++){
                float ax, ay, bx, by;
                unpk2(vA[j], ax, ay);
                unpk2(vB[j], bx, by);
                re[j] = pk2(ax, bx);
                im[j] = pk2(ay, by);
            }
            warp_fft320_soa(re, im, lane, k2);

            u64* gA = g_grid + ((size_t)b*RES + qyA) * RES;
            u64* gB = gA + RES;
            #pragma unroll
            for (int k1 = 0; k1 < 10; k1++){
                float rA, rB, iA, iB;
                unpk2(re[k1], rA, rB);
                unpk2(im[k1], iA, iB);
                gA[32*k1 + k2] = pk2(rA, iA);
                gB[32*k1 + k2] = pk2(rB, iB);
            }
            // publish (release): fence then relaxed atomic
            __syncthreads();            // all warps' stores issued before publish
            __threadfence();
            if (tid == 0) atomicAdd(&g_done[b], 1u);
        } else {
            // ---------------- col-unit: dual column FFTs + output ----------------
            unsigned u = t - 640u;
            int b  = u / 20;
            int v0 = (u % 20) * 16;
            u64 (*shre)[361] = (u64(*)[361])buf;          // [8][361]
            u64 (*shim)[361] = (u64(*)[361])(buf + 8*361);

            // wait for all 20 row-units of batch b
            if (tid == 0){
                unsigned v;
                do {
                    v = *(volatile unsigned*)&g_done[b];
                    if (v < 20u) __nanosleep(200);
                } while (v < 20u);
            }
            __syncthreads();
            __threadfence();            // acquire

            const u64* gb = g_grid + (size_t)b * NPIX;
            for (int e = tid; e < 2560; e += 256){
                int r = e >> 3, pp = e & 7;
                float4 q = *(const float4*)(gb + r*RES + v0 + 2*pp);
                shre[pp][PADIX(r)] = pk2(q.x, q.z);
                shim[pp][PADIX(r)] = pk2(q.y, q.w);
            }
            __syncthreads();

            u64 re[10], im[10];
            #pragma unroll
            for (int j = 0; j < 10; j++){
                re[j] = shre[warp][PADIX(10*lane + j)];
                im[j] = shim[warp][PADIX(10*lane + j)];
            }
            warp_fft320_soa(re, im, lane, k2);
            #pragma unroll
            for (int k1 = 0; k1 < 10; k1++){
                shre[warp][PADIX(32*k1 + k2)] = re[k1];
                shim[warp][PADIX(32*k1 + k2)] = im[k1];
            }
            __syncthreads();

            float* outR = out + ((size_t)b*2 + 0) * NPIX;
            float* outI = out + ((size_t)b*2 + 1) * NPIX;
            int nj0 = v0 + 160; if (nj0 >= RES) nj0 -= RES;
            for (int e = tid; e < 2560; e += 256){
                int uu = e >> 3, pp = e & 7;
                float rA, rB, iA, iB;
                unpk2(shre[pp][PADIX(uu)], rA, rB);
                unpk2(shim[pp][PADIX(uu)], iA, iB);
                int ni = uu + 160; if (ni >= RES) ni -= RES;
                int colA = v0 + 2*pp;
                float sgnA = ((uu + colA) & 1) ? -1.f : 1.f;
                float sgnB = -sgnA;
                int o = ni*RES + nj0 + 2*pp;
                *(float2*)(outR + o) = make_float2(sgnA*rA, sgnB*rB);
                *(float2*)(outI + o) = make_float2(sgnA*iA, sgnB*iB);
            }
        }
        __syncthreads();   // shared buffer reuse barrier before next unit
    }
}

// ---------------- launch ----------------
extern "C" void kernel_launch(void* const* d_in, const int* in_sizes, int n_in,
                              void* d_out, int out_size){
    const float* ksp = (const float*)d_in[0];   // (32,1,320,320,2) f32
    float* out = (float*)d_out;                 // (32,1,2,320,320) f32

    k_reset<<<1, 32>>>();
    k_fused<<<592, 256>>>(ksp, out);            // 4 blocks/SM nominal; ticket queue
}